// round 4
// baseline (speedup 1.0000x reference)
#include <cuda_runtime.h>

typedef unsigned long long ull;

#define LOG2E 1.4426950408889634f
#define BB 32
#define NN 512
#define NH 8
#define ND 8
#define NF 128

// ---------------- scratch ----------------
__device__ float g_x[BB * NN * NH * ND];     // layer-1 output, [b][n][h*8+d]
__device__ float g_h0p[BB][4][ND];           // layer-2 per-chunk partials for node 0

// ---------------- helpers ----------------
__device__ __forceinline__ float ex2f(float x) {
    float r; asm("ex2.approx.f32 %0, %1;" : "=f"(r) : "f"(x)); return r;
}
__device__ __forceinline__ void ffma2(ull &acc, ull a, ull b) {
    asm("fma.rn.f32x2 %0, %1, %2, %0;" : "+l"(acc) : "l"(a), "l"(b));
}
__device__ __forceinline__ ull pack2(float x) {
    ull r; asm("mov.b64 %0, {%1, %1};" : "=l"(r) : "f"(x)); return r;
}
__device__ __forceinline__ float lrelu02(float x) { return fmaxf(x, 0.2f * x); }
__device__ __forceinline__ float eluf(float x) { return x > 0.f ? x : expm1f(x); }

__device__ __forceinline__ unsigned f2s(float f) {
    unsigned u = __float_as_uint(f);
    return u ^ ((u & 0x80000000u) ? 0xFFFFFFFFu : 0x80000000u);
}

__device__ __forceinline__ int lower_bound512(const ull* arr, ull X) {
    int c = 0;
#pragma unroll
    for (int s = 256; s >= 1; s >>= 1) {
        int t = c + s;
        if (t <= NN && arr[t - 1] < X) c = t;
    }
    return c;
}

// =====================================================================
// K2: fused projection + layer-1 attention (branch-factorized softmax).
// grid (32, 8), 512 threads, dynamic smem, 2 blocks/SM.
// =====================================================================
struct K2S {
    ull bufA[2][NN];        // double-buffered sort workspace / final sorted s1 keys in bufA[0]
    ull bufB[2][NN];        // same for s2 keys
    float SUV[NN][17];      // [0..7]=U prefix, [8..15]=V prefix (sorted-s2 order)
    float E1s[NN];
    float F1s[NN];
    float PE[NN];           // inclusive prefix of E1 in sorted-s1 order
    float PF[NN];
    float wsum[16][17];
    float off16[16][17];
    float wsum2[16][2];
    float off2[16][2];
    float redbuf[16];
    unsigned short rankB[NN];
    ull Wsm[128][4];        // W_h packed as f32x2 pairs
};

// dual prefix scan over 512 elements (components A, B), 2nd level via warp scan
__device__ __forceinline__ void scan2b(float* A, float* B, float (*wsum2)[2],
                                       float (*off2)[2], int tid) {
    const int lane = tid & 31, wid = tid >> 5;
    float a = A[tid], b = B[tid];
#pragma unroll
    for (int s = 1; s < 32; s <<= 1) {
        float ta = __shfl_up_sync(0xffffffffu, a, s);
        float tb = __shfl_up_sync(0xffffffffu, b, s);
        if (lane >= s) { a += ta; b += tb; }
    }
    if (lane == 31) { wsum2[wid][0] = a; wsum2[wid][1] = b; }
    __syncthreads();
    if (wid < 2) {
        float x0 = (lane < 16) ? wsum2[lane][wid] : 0.f;
        float x = x0;
#pragma unroll
        for (int s = 1; s < 16; s <<= 1) {
            float t = __shfl_up_sync(0xffffffffu, x, s);
            if (lane >= s) x += t;
        }
        if (lane < 16) off2[lane][wid] = x - x0;   // exclusive prefix
    }
    __syncthreads();
    A[tid] = a + off2[wid][0];
    B[tid] = b + off2[wid][1];
    __syncthreads();
}

// 16-component prefix scan over 512 rows of A[NN][17]
__device__ __forceinline__ void scan16(float (*A)[17], float (*wsum)[17],
                                       float (*off16)[17], int tid) {
    const int lane = tid & 31, wid = tid >> 5;
    float v[16];
#pragma unroll
    for (int d = 0; d < 16; d++) v[d] = A[tid][d];
#pragma unroll
    for (int s = 1; s < 32; s <<= 1) {
#pragma unroll
        for (int d = 0; d < 16; d++) {
            float t = __shfl_up_sync(0xffffffffu, v[d], s);
            if (lane >= s) v[d] += t;
        }
    }
    if (lane == 31) {
#pragma unroll
        for (int d = 0; d < 16; d++) wsum[wid][d] = v[d];
    }
    __syncthreads();
    {   // warp w scans component w across the 16 warp sums
        float x0 = (lane < 16) ? wsum[lane][wid] : 0.f;
        float x = x0;
#pragma unroll
        for (int s = 1; s < 16; s <<= 1) {
            float t = __shfl_up_sync(0xffffffffu, x, s);
            if (lane >= s) x += t;
        }
        if (lane < 16) off16[lane][wid] = x - x0;
    }
    __syncthreads();
#pragma unroll
    for (int d = 0; d < 16; d++) A[tid][d] = v[d] + off16[wid][d];
    __syncthreads();
}

__global__ __launch_bounds__(512, 2) void k2_att1(const float* __restrict__ nf,
                                                  const float* __restrict__ Ws,
                                                  const float* __restrict__ As) {
    extern __shared__ char raw[];
    K2S& S = *reinterpret_cast<K2S*>(raw);
    const int b = blockIdx.x, h = blockIdx.y, tid = threadIdx.x;

    // ---- load W_h into shared ----
    {
        float* Wf = reinterpret_cast<float*>(S.Wsm);
        const float* wsrc = Ws + h * (NF * ND);
        Wf[tid] = wsrc[tid];
        Wf[tid + 512] = wsrc[tid + 512];
    }
    __syncthreads();

    // ---- projection: wh[0..7] = nf[b, tid, :] @ W_h (LDS.128 W reads) ----
    const float4* row = reinterpret_cast<const float4*>(nf + (size_t)(b * NN + tid) * NF);
    ull acc[4] = {0, 0, 0, 0};
#pragma unroll 4
    for (int f4 = 0; f4 < 32; f4++) {
        float4 v = row[f4];
        float vs[4] = {v.x, v.y, v.z, v.w};
#pragma unroll
        for (int u = 0; u < 4; u++) {
            ull p = pack2(vs[u]);
            const ulonglong2* wr = reinterpret_cast<const ulonglong2*>(S.Wsm[f4 * 4 + u]);
            ulonglong2 w01 = wr[0], w23 = wr[1];
            ffma2(acc[0], p, w01.x);
            ffma2(acc[1], p, w01.y);
            ffma2(acc[2], p, w23.x);
            ffma2(acc[3], p, w23.y);
        }
    }
    float wv[8];
#pragma unroll
    for (int k = 0; k < 4; k++) {
        wv[2 * k]     = __uint_as_float((unsigned)(acc[k] & 0xffffffffu));
        wv[2 * k + 1] = __uint_as_float((unsigned)(acc[k] >> 32));
    }

    const float* a = As + h * 16;
    float s1 = 0.f, s2 = 0.f;
#pragma unroll
    for (int d = 0; d < 8; d++) { s1 += wv[d] * a[d]; s2 += wv[d] * a[8 + d]; }
    const float s1L = s1 * LOG2E, s2L = s2 * LOG2E;

    // ---- block max M of s1L ----
    float m = s1L;
#pragma unroll
    for (int o = 16; o >= 1; o >>= 1) m = fmaxf(m, __shfl_xor_sync(0xffffffffu, m, o));
    if ((tid & 31) == 0) S.redbuf[tid >> 5] = m;
    __syncthreads();
    float M = S.redbuf[0];
#pragma unroll
    for (int w = 1; w < 16; w++) M = fmaxf(M, S.redbuf[w]);

    const float E1 = ex2f(s1L - M);
    const float F1 = ex2f(0.2f * (s1L - M));
    S.E1s[tid] = E1;
    S.F1s[tid] = F1;

    // ---- register bitonic sort, double-buffered cross-warp stages ----
    ull va = (((ull)f2s(s1L)) << 32) | (unsigned)tid;
    ull vb = (((ull)f2s(s2L)) << 32) | (unsigned)tid;
    int p = 0;
    for (int k = 2; k <= NN; k <<= 1) {
        for (int s = k >> 1; s >= 1; s >>= 1) {
            const bool keepmin = (((tid & s) == 0) == ((tid & k) == 0));
            ull oa, ob;
            if (s >= 32) {
                S.bufA[p][tid] = va; S.bufB[p][tid] = vb;
                __syncthreads();
                oa = S.bufA[p][tid ^ s]; ob = S.bufB[p][tid ^ s];
                p ^= 1;
            } else {
                oa = __shfl_xor_sync(0xffffffffu, va, s);
                ob = __shfl_xor_sync(0xffffffffu, vb, s);
            }
            va = ((va < oa) == keepmin) ? va : oa;
            vb = ((vb < ob) == keepmin) ? vb : ob;
        }
    }
    // final sorted arrays for binary search (safe: last stage read buffer 1)
    S.bufA[0][tid] = va;
    S.bufB[0][tid] = vb;
    {
        int ja = (int)(va & 0xffffffffu);
        int jb = (int)(vb & 0xffffffffu);
        S.rankB[jb] = (unsigned short)tid;
        S.PE[tid] = S.E1s[ja];
        S.PF[tid] = S.F1s[ja];
    }
    __syncthreads();
    scan2b(S.PE, S.PF, S.wsum2, S.off2, tid);
    const float TE = S.PE[NN - 1];

    // ---- per thread j: Z_j, scatter U_j/V_j into sorted-s2 slot ----
    const int c = lower_bound512(S.bufA[0], ((ull)f2s(-s2L)) << 32);
    const float sumEge = TE - (c > 0 ? S.PE[c - 1] : 0.f);
    const float preF   = (c > 0 ? S.PF[c - 1] : 0.f);
    const float mj = lrelu02(M + s2L);
    const float E2 = ex2f(s2L + M - mj);
    const float F2 = ex2f(0.2f * (s2L + M) - mj);
    const float rz = 1.0f / (E2 * sumEge + F2 * preF);
    const float ue = E2 * rz, vf = F2 * rz;

    const int r = S.rankB[tid];
#pragma unroll
    for (int d = 0; d < 8; d++) {
        S.SUV[r][d]     = ue * wv[d];
        S.SUV[r][8 + d] = vf * wv[d];
    }
    __syncthreads();
    scan16(S.SUV, S.wsum, S.off16, tid);

    float TU[8];
#pragma unroll
    for (int d = 0; d < 8; d++) TU[d] = S.SUV[NN - 1][d];

    // ---- per thread i: h_i = E1*SufU + F1*PreV, elu, store ----
    const int c2 = lower_bound512(S.bufB[0], ((ull)f2s(-s1L)) << 32);
    float res[8];
#pragma unroll
    for (int d = 0; d < 8; d++) {
        float su = TU[d] - (c2 > 0 ? S.SUV[c2 - 1][d] : 0.f);
        float pv = (c2 > 0 ? S.SUV[c2 - 1][8 + d] : 0.f);
        res[d] = eluf(E1 * su + F1 * pv);
    }
    float4* xo = reinterpret_cast<float4*>(g_x + (size_t)(b * NN + tid) * (NH * ND) + h * ND);
    xo[0] = make_float4(res[0], res[1], res[2], res[3]);
    xo[1] = make_float4(res[4], res[5], res[6], res[7]);
}

// =====================================================================
// K34: layer-2 projection + attention (row 0), chunked over j.
// grid (32, 4), 512 threads; each block redundantly projects all rows,
// sorts s1 once, outputs partial weighted sum for its 128-j chunk.
// =====================================================================
__global__ __launch_bounds__(512) void k34(const float* __restrict__ Wout,
                                           const float* __restrict__ aout) {
    __shared__ float Wo[64 * 8];
    __shared__ float ao[16];
    __shared__ float whs[128][9];
    __shared__ float s2s[128];
    __shared__ float E1s[NN], F1s[NN], PE[NN], PF[NN];
    __shared__ ull bufA[2][NN];
    __shared__ float wsum2[16][2], off2[16][2];
    __shared__ float redbuf[16];
    __shared__ float wpart[4][8];
    __shared__ float bc0[1];

    const int b = blockIdx.x, jc = blockIdx.y, tid = threadIdx.x;
    const int lane = tid & 31, wid = tid >> 5;

    Wo[tid] = Wout[tid];
    if (tid < 16) ao[tid] = aout[tid];
    __syncthreads();

    // projection of row tid
    const float4* row = reinterpret_cast<const float4*>(g_x + (size_t)(b * NN + tid) * 64);
    float acc[8] = {0, 0, 0, 0, 0, 0, 0, 0};
#pragma unroll 4
    for (int f4 = 0; f4 < 16; f4++) {
        float4 v = row[f4];
        float vs[4] = {v.x, v.y, v.z, v.w};
#pragma unroll
        for (int u = 0; u < 4; u++) {
            const float* wr = &Wo[(f4 * 4 + u) * 8];
#pragma unroll
            for (int d = 0; d < 8; d++) acc[d] += vs[u] * wr[d];
        }
    }
    float s1 = 0.f, s2 = 0.f;
#pragma unroll
    for (int d = 0; d < 8; d++) { s1 += acc[d] * ao[d]; s2 += acc[d] * ao[8 + d]; }
    const float s1L = s1 * LOG2E, s2L = s2 * LOG2E;

    if ((tid >> 7) == jc) {
        const int jl = tid & 127;
        s2s[jl] = s2L;
#pragma unroll
        for (int d = 0; d < 8; d++) whs[jl][d] = acc[d];
    }
    if (tid == 0) bc0[0] = s1L;

    float m = s1L;
#pragma unroll
    for (int o = 16; o >= 1; o >>= 1) m = fmaxf(m, __shfl_xor_sync(0xffffffffu, m, o));
    if (lane == 0) redbuf[wid] = m;
    __syncthreads();
    float M = redbuf[0];
#pragma unroll
    for (int w = 1; w < 16; w++) M = fmaxf(M, redbuf[w]);

    E1s[tid] = ex2f(s1L - M);
    F1s[tid] = ex2f(0.2f * (s1L - M));

    ull va = (((ull)f2s(s1L)) << 32) | (unsigned)tid;
    int p = 0;
    for (int k = 2; k <= NN; k <<= 1) {
        for (int s = k >> 1; s >= 1; s >>= 1) {
            const bool keepmin = (((tid & s) == 0) == ((tid & k) == 0));
            ull oa;
            if (s >= 32) {
                bufA[p][tid] = va;
                __syncthreads();
                oa = bufA[p][tid ^ s];
                p ^= 1;
            } else {
                oa = __shfl_xor_sync(0xffffffffu, va, s);
            }
            va = ((va < oa) == keepmin) ? va : oa;
        }
    }
    bufA[0][tid] = va;
    {
        int ja = (int)(va & 0xffffffffu);
        PE[tid] = E1s[ja];
        PF[tid] = F1s[ja];
    }
    __syncthreads();
    scan2b(PE, PF, wsum2, off2, tid);
    const float TE = PE[NN - 1];

    // chunk j-threads compute attention weight of node 0 on j
    if (tid < 128) {
        const float s2j = s2s[tid];
        const int c = lower_bound512(bufA[0], ((ull)f2s(-s2j)) << 32);
        const float sumEge = TE - (c > 0 ? PE[c - 1] : 0.f);
        const float preF   = (c > 0 ? PF[c - 1] : 0.f);
        const float mj = lrelu02(M + s2j);
        const float E2 = ex2f(s2j + M - mj);
        const float F2 = ex2f(0.2f * (s2j + M) - mj);
        const float Z = E2 * sumEge + F2 * preF;

        const float s1L0 = bc0[0];
        const float e0 = (s1L0 + s2j >= 0.f) ? ex2f(s1L0 - M) * E2
                                             : ex2f(0.2f * (s1L0 - M)) * F2;
        const float wj = e0 / Z;

        float pv[8];
#pragma unroll
        for (int d = 0; d < 8; d++) pv[d] = wj * whs[tid][d];
#pragma unroll
        for (int d = 0; d < 8; d++) {
#pragma unroll
            for (int o = 16; o >= 1; o >>= 1)
                pv[d] += __shfl_xor_sync(0xffffffffu, pv[d], o);
        }
        if (lane == 0) {
#pragma unroll
            for (int d = 0; d < 8; d++) wpart[wid][d] = pv[d];
        }
    }
    __syncthreads();
    if (tid < 8) {
        g_h0p[b][jc][tid] = wpart[0][tid] + wpart[1][tid] + wpart[2][tid] + wpart[3][tid];
    }
}

// =====================================================================
// K5: elu(h0) -> concat feats -> lin1 -> prelu -> bn -> lin2
// grid 1, 256 threads
// =====================================================================
__global__ __launch_bounds__(256) void k5_mlp(const float* __restrict__ feats,
                                              const float* __restrict__ lin1w,
                                              const float* __restrict__ lin1b,
                                              const float* __restrict__ prelua,
                                              const float* __restrict__ gamma,
                                              const float* __restrict__ beta,
                                              const float* __restrict__ lin2w,
                                              const float* __restrict__ lin2b,
                                              float* __restrict__ out) {
    const int tid = threadIdx.x;
    const int b = tid >> 3, k = tid & 7;

    float gat[8];
#pragma unroll
    for (int d = 0; d < 8; d++) {
        float v = g_h0p[b][0][d] + g_h0p[b][1][d] + g_h0p[b][2][d] + g_h0p[b][3][d];
        gat[d] = eluf(v);
    }

    const float* w = lin1w + k * 136;
    const float* fr = feats + b * 128;
    float z = lin1b[k];
#pragma unroll 8
    for (int f = 0; f < 128; f++) z += fr[f] * w[f];
#pragma unroll
    for (int d = 0; d < 8; d++) z += gat[d] * w[128 + d];

    const float pa = prelua[0];
    z = (z >= 0.f) ? z : pa * z;
    z = z * rsqrtf(1.0f + 1e-5f) * gamma[k] + beta[k];

    float v = z * lin2w[k];
    v += __shfl_xor_sync(0xffffffffu, v, 4);
    v += __shfl_xor_sync(0xffffffffu, v, 2);
    v += __shfl_xor_sync(0xffffffffu, v, 1);
    if (k == 0) out[b] = v + lin2b[0];
}

// =====================================================================
extern "C" void kernel_launch(void* const* d_in, const int* in_sizes, int n_in,
                              void* d_out, int out_size) {
    (void)in_sizes; (void)n_in; (void)out_size;
    const float* feats  = (const float*)d_in[0];
    const float* nf     = (const float*)d_in[1];
    const float* Ws     = (const float*)d_in[2];
    const float* As     = (const float*)d_in[3];
    const float* Wout   = (const float*)d_in[4];
    const float* aout   = (const float*)d_in[5];
    const float* lin1w  = (const float*)d_in[6];
    const float* lin1b  = (const float*)d_in[7];
    const float* prelua = (const float*)d_in[8];
    const float* gamma  = (const float*)d_in[9];
    const float* beta   = (const float*)d_in[10];
    const float* lin2w  = (const float*)d_in[11];
    const float* lin2b  = (const float*)d_in[12];
    float* out = (float*)d_out;

    static bool attr_done = false;
    if (!attr_done) {
        cudaFuncSetAttribute(k2_att1, cudaFuncAttributeMaxDynamicSharedMemorySize,
                             (int)sizeof(K2S));
        attr_done = true;
    }

    k2_att1<<<dim3(32, 8), 512, sizeof(K2S)>>>(nf, Ws, As);
    k34<<<dim3(32, 4), 512>>>(Wout, aout);
    k5_mlp<<<1, 256>>>(feats, lin1w, lin1b, prelua, gamma, beta, lin2w, lin2b, out);
}

// round 6
// speedup vs baseline: 1.2498x; 1.2498x over previous
#include <cuda_runtime.h>

typedef unsigned long long ull;

#define LOG2E 1.4426950408889634f
#define BB 32
#define NN 512
#define NH 8
#define ND 8
#define NF 128
#define KEYMASK 0xFFFFFE00u

// ---------------- scratch ----------------
__device__ float g_Wh1[BB * NH * NN * ND];   // [b][h][n][d]
__device__ float g_x[BB * NN * NH * ND];     // [b][n][h*8+d]
__device__ float g_wh2[BB * NN * ND];
__device__ float g_s1[BB * NN];
__device__ float g_s2[BB * NN];
__device__ float g_h0p[BB][4][ND];

// ---------------- helpers ----------------
__device__ __forceinline__ float ex2f(float x) {
    float r; asm("ex2.approx.f32 %0, %1;" : "=f"(r) : "f"(x)); return r;
}
__device__ __forceinline__ void ffma2(ull &acc, ull a, ull b) {
    asm("fma.rn.f32x2 %0, %1, %2, %0;" : "+l"(acc) : "l"(a), "l"(b));
}
__device__ __forceinline__ ull packf2(float lo, float hi) {
    ull r; asm("mov.b64 %0, {%1, %2};" : "=l"(r) : "f"(lo), "f"(hi)); return r;
}
__device__ __forceinline__ float lof(ull v) { return __uint_as_float((unsigned)(v & 0xffffffffu)); }
__device__ __forceinline__ float hif(ull v) { return __uint_as_float((unsigned)(v >> 32)); }
__device__ __forceinline__ float lrelu02(float x) { return fmaxf(x, 0.2f * x); }
__device__ __forceinline__ float eluf(float x) { return x > 0.f ? x : ex2f(x * LOG2E) - 1.0f; }
__device__ __forceinline__ unsigned f2s(float f) {
    unsigned u = __float_as_uint(f);
    return u ^ ((u & 0x80000000u) ? 0xFFFFFFFFu : 0x80000000u);
}
// lower_bound over 512 sorted u32 (10 steps, result in [0,512])
__device__ __forceinline__ int lb512(const unsigned* arr, unsigned X) {
    int c = 0;
#pragma unroll
    for (int s = 512; s >= 1; s >>= 1) {
        int t = c + s;
        if (t <= 512 && arr[t - 1] < X) c = t;
    }
    return c;
}

// =====================================================================
// kA: Wh[b,h,n,d] = nf @ W  as one [16384,128]@[128,64] GEMM.
// grid 128, 512 threads, 4x4 thread tiles, f32x2 k-pair accumulation.
// =====================================================================
#define KA_SMEM (128 * 128 * 4 + 64 * 132 * 4)
__global__ __launch_bounds__(512, 1) void kA(const float* __restrict__ nf,
                                             const float* __restrict__ Ws) {
    extern __shared__ float sm[];
    float* As = sm;                 // [128 rows][128 k] row-major
    float* Bt = sm + 128 * 128;     // [64 c][132] (k padded; 132 % 4 == 0 for LDS.128)
    const int t = threadIdx.x, blk = blockIdx.x;

    // stage A (coalesced, row-major)
    const float4* gA = reinterpret_cast<const float4*>(nf) + (size_t)blk * 128 * 32;
    float4* As4 = reinterpret_cast<float4*>(As);
#pragma unroll
    for (int i = 0; i < 8; i++) {
        int idx4 = t + 512 * i;
        As4[idx4] = gA[idx4];
    }
    // stage Bt: Bt[c][k] = Ws[c>>3][k][c&7]
#pragma unroll
    for (int i = 0; i < 16; i++) {
        int idx = t + 512 * i;
        int c = idx & 63, k = idx >> 6;
        Bt[c * 132 + k] = Ws[(c >> 3) * 1024 + k * 8 + (c & 7)];
    }
    __syncthreads();

    const int tx = t & 15, ty = t >> 4;   // cols c=tx*4.., rows r=ty*4..
    ull acc2[4][4];
#pragma unroll
    for (int r = 0; r < 4; r++)
#pragma unroll
        for (int c = 0; c < 4; c++) acc2[r][c] = 0ull;

#pragma unroll 2
    for (int k4 = 0; k4 < 32; k4++) {
        ull ap[4][2], bp[4][2];
#pragma unroll
        for (int r = 0; r < 4; r++) {
            float4 a = *reinterpret_cast<const float4*>(&As[(ty * 4 + r) * 128 + k4 * 4]);
            ap[r][0] = packf2(a.x, a.y);
            ap[r][1] = packf2(a.z, a.w);
        }
#pragma unroll
        for (int c = 0; c < 4; c++) {
            float4 bq = *reinterpret_cast<const float4*>(&Bt[(tx * 4 + c) * 132 + k4 * 4]);
            bp[c][0] = packf2(bq.x, bq.y);
            bp[c][1] = packf2(bq.z, bq.w);
        }
#pragma unroll
        for (int r = 0; r < 4; r++)
#pragma unroll
            for (int c = 0; c < 4; c++) {
                ffma2(acc2[r][c], ap[r][0], bp[c][0]);
                ffma2(acc2[r][c], ap[r][1], bp[c][1]);
            }
    }

    const int c0 = tx * 4, h = c0 >> 3, d0 = c0 & 7;
#pragma unroll
    for (int r = 0; r < 4; r++) {
        int gr = blk * 128 + ty * 4 + r;
        int b = gr >> 9, n = gr & 511;
        float o[4];
#pragma unroll
        for (int c = 0; c < 4; c++) o[c] = lof(acc2[r][c]) + hif(acc2[r][c]);
        *reinterpret_cast<float4*>(&g_Wh1[(((size_t)(b * NH + h)) * NN + n) * ND + d0]) =
            make_float4(o[0], o[1], o[2], o[3]);
    }
}

// =====================================================================
// kB: layer-1 attention per (b,h), branch-factorized softmax.
// grid (32, 8), 512 threads, 2 blocks/SM.
// =====================================================================
struct K2S {
    float SUV[16 * 640];        // comp-major, 32 chunks x (16 data + 4 pad)
    ull sbuf[2][NN];            // packed (keyA<<32 | keyB) cross-warp exchange
    unsigned sortedA[NN];
    unsigned sortedB[NN];
    float E1s[NN], F1s[NN];
    float PE[NN], PF[NN];
    float wsum2[16][2], off2[16][2];
    float redbuf[16];
    float av[16];
    unsigned short rankB[NN];
};
__device__ __forceinline__ int suv_addr(int c, int r) {
    return c * 640 + (r >> 4) * 20 + (r & 15);
}

__device__ __forceinline__ void scan2b(float* A, float* B, float (*wsum2)[2],
                                       float (*off2)[2], int tid) {
    const int lane = tid & 31, wid = tid >> 5;
    float a = A[tid], b = B[tid];
#pragma unroll
    for (int s = 1; s < 32; s <<= 1) {
        float ta = __shfl_up_sync(0xffffffffu, a, s);
        float tb = __shfl_up_sync(0xffffffffu, b, s);
        if (lane >= s) { a += ta; b += tb; }
    }
    if (lane == 31) { wsum2[wid][0] = a; wsum2[wid][1] = b; }
    __syncthreads();
    if (wid < 2) {
        float x0 = (lane < 16) ? wsum2[lane][wid] : 0.f;
        float x = x0;
#pragma unroll
        for (int s = 1; s < 16; s <<= 1) {
            float tv = __shfl_up_sync(0xffffffffu, x, s);
            if (lane >= s) x += tv;
        }
        if (lane < 16) off2[lane][wid] = x - x0;
    }
    __syncthreads();
    A[tid] = a + off2[wid][0];
    B[tid] = b + off2[wid][1];
    __syncthreads();
}

__global__ __launch_bounds__(512, 2) void kB(const float* __restrict__ As_g) {
    extern __shared__ char raw[];
    K2S& S = *reinterpret_cast<K2S*>(raw);
    const int b = blockIdx.x, h = blockIdx.y, tid = threadIdx.x;
    const int lane = tid & 31, wid = tid >> 5;

    if (tid < 16) S.av[tid] = As_g[h * 16 + tid];

    // wh row (precomputed by kA)
    const float4* whp = reinterpret_cast<const float4*>(
        g_Wh1 + (((size_t)(b * NH + h)) * NN + tid) * ND);
    float4 w0 = whp[0], w1 = whp[1];
    float wv[8] = {w0.x, w0.y, w0.z, w0.w, w1.x, w1.y, w1.z, w1.w};
    __syncthreads();

    float s1 = 0.f, s2 = 0.f;
#pragma unroll
    for (int d = 0; d < 8; d++) { s1 += wv[d] * S.av[d]; s2 += wv[d] * S.av[8 + d]; }
    const float s1L = s1 * LOG2E, s2L = s2 * LOG2E;

    // block max M of s1L
    float m = s1L;
#pragma unroll
    for (int o = 16; o >= 1; o >>= 1) m = fmaxf(m, __shfl_xor_sync(0xffffffffu, m, o));
    if (lane == 0) S.redbuf[wid] = m;
    __syncthreads();
    float M = S.redbuf[0];
#pragma unroll
    for (int w = 1; w < 16; w++) M = fmaxf(M, S.redbuf[w]);

    const float E1 = ex2f(s1L - M);
    const float F1 = ex2f(0.2f * (s1L - M));
    S.E1s[tid] = E1;
    S.F1s[tid] = F1;

    // dual 32-bit truncated-key bitonic sort (register-resident, packed exchanges)
    unsigned ka = (f2s(s1L) & KEYMASK) | (unsigned)tid;
    unsigned kb = (f2s(s2L) & KEYMASK) | (unsigned)tid;
    int p = 0;
    for (int k = 2; k <= NN; k <<= 1) {
        for (int s = k >> 1; s >= 1; s >>= 1) {
            const bool keepmin = (((tid & s) == 0) == ((tid & k) == 0));
            unsigned oa, ob;
            if (s >= 32) {
                S.sbuf[p][tid] = (((ull)ka) << 32) | kb;
                __syncthreads();
                ull o = S.sbuf[p][tid ^ s];
                oa = (unsigned)(o >> 32); ob = (unsigned)o;
                p ^= 1;
            } else {
                oa = __shfl_xor_sync(0xffffffffu, ka, s);
                ob = __shfl_xor_sync(0xffffffffu, kb, s);
            }
            ka = ((ka < oa) == keepmin) ? ka : oa;
            kb = ((kb < ob) == keepmin) ? kb : ob;
        }
    }
    S.sortedA[tid] = ka;
    S.sortedB[tid] = kb;
    {
        int ja = (int)(ka & 511u);
        int jb = (int)(kb & 511u);
        S.rankB[jb] = (unsigned short)tid;
        S.PE[tid] = S.E1s[ja];
        S.PF[tid] = S.F1s[ja];
    }
    __syncthreads();
    scan2b(S.PE, S.PF, S.wsum2, S.off2, tid);
    const float TE = S.PE[NN - 1];

    // per thread j: Z_j, scatter U/V into sorted-s2 slot (comp-major)
    const int c = lb512(S.sortedA, f2s(-s2L) & KEYMASK);
    const float sumEge = TE - (c > 0 ? S.PE[c - 1] : 0.f);
    const float preF   = (c > 0 ? S.PF[c - 1] : 0.f);
    const float mj = lrelu02(M + s2L);
    const float E2 = ex2f(s2L + M - mj);
    const float F2 = ex2f(0.2f * (s2L + M) - mj);
    const float rz = 1.0f / (E2 * sumEge + F2 * preF);
    const float ue = E2 * rz, vf = F2 * rz;

    const int r = S.rankB[tid];
#pragma unroll
    for (int d = 0; d < 8; d++) {
        S.SUV[suv_addr(d, r)]     = ue * wv[d];
        S.SUV[suv_addr(8 + d, r)] = vf * wv[d];
    }
    __syncthreads();

    // warp-per-component scan: warp wid scans component wid over 512 rows
    {
        float4* base = reinterpret_cast<float4*>(S.SUV) + wid * 160 + lane * 5;
        float4 q0 = base[0], q1 = base[1], q2 = base[2], q3 = base[3];
        float v[16] = {q0.x, q0.y, q0.z, q0.w, q1.x, q1.y, q1.z, q1.w,
                       q2.x, q2.y, q2.z, q2.w, q3.x, q3.y, q3.z, q3.w};
#pragma unroll
        for (int i = 1; i < 16; i++) v[i] += v[i - 1];
        float tot = v[15], inc = tot;
#pragma unroll
        for (int s = 1; s < 32; s <<= 1) {
            float tv = __shfl_up_sync(0xffffffffu, inc, s);
            if (lane >= s) inc += tv;
        }
        float off = inc - tot;
#pragma unroll
        for (int i = 0; i < 16; i++) v[i] += off;
        base[0] = make_float4(v[0], v[1], v[2], v[3]);
        base[1] = make_float4(v[4], v[5], v[6], v[7]);
        base[2] = make_float4(v[8], v[9], v[10], v[11]);
        base[3] = make_float4(v[12], v[13], v[14], v[15]);
    }
    __syncthreads();

    float TU[8];
#pragma unroll
    for (int d = 0; d < 8; d++) TU[d] = S.SUV[suv_addr(d, NN - 1)];

    // per thread i: h_i = E1*SufU + F1*PreV, elu, store
    const int c2 = lb512(S.sortedB, f2s(-s1L) & KEYMASK);
    float res[8];
#pragma unroll
    for (int d = 0; d < 8; d++) {
        float su = TU[d] - (c2 > 0 ? S.SUV[suv_addr(d, c2 - 1)] : 0.f);
        float pv = (c2 > 0 ? S.SUV[suv_addr(8 + d, c2 - 1)] : 0.f);
        res[d] = eluf(E1 * su + F1 * pv);
    }
    float4* xo = reinterpret_cast<float4*>(g_x + ((size_t)(b * NN + tid)) * (NH * ND) + h * ND);
    xo[0] = make_float4(res[0], res[1], res[2], res[3]);
    xo[1] = make_float4(res[4], res[5], res[6], res[7]);
}

// =====================================================================
// kC: layer-2 projection. grid 128, 128 threads; thread = one row.
// =====================================================================
__global__ __launch_bounds__(128) void kC(const float* __restrict__ Wout,
                                          const float* __restrict__ aout) {
    __shared__ float Wot[8][72];   // Wot[d][k] = Wout[k][d]; 72 % 4 == 0 for LDS.128
    __shared__ float ao[16];
    const int t = threadIdx.x;
    const int row = blockIdx.x * 128 + t;
#pragma unroll
    for (int i = 0; i < 4; i++) {
        int idx = t + 128 * i;
        Wot[idx & 7][idx >> 3] = Wout[idx];
    }
    if (t < 16) ao[t] = aout[t];
    __syncthreads();

    const float4* xr = reinterpret_cast<const float4*>(g_x + (size_t)row * 64);
    float4 xv[16];
#pragma unroll
    for (int q = 0; q < 16; q++) xv[q] = xr[q];
    ull xp[32];
#pragma unroll
    for (int q = 0; q < 16; q++) {
        xp[2 * q]     = packf2(xv[q].x, xv[q].y);
        xp[2 * q + 1] = packf2(xv[q].z, xv[q].w);
    }
    float acc[8];
#pragma unroll
    for (int d = 0; d < 8; d++) {
        ull a2 = 0ull;
#pragma unroll
        for (int q = 0; q < 16; q++) {
            float4 bq = *reinterpret_cast<const float4*>(&Wot[d][q * 4]);
            ffma2(a2, xp[2 * q], packf2(bq.x, bq.y));
            ffma2(a2, xp[2 * q + 1], packf2(bq.z, bq.w));
        }
        acc[d] = lof(a2) + hif(a2);
    }
    float s1 = 0.f, s2 = 0.f;
#pragma unroll
    for (int d = 0; d < 8; d++) { s1 += acc[d] * ao[d]; s2 += acc[d] * ao[8 + d]; }
    g_s1[row] = s1 * LOG2E;
    g_s2[row] = s2 * LOG2E;
    float4* o = reinterpret_cast<float4*>(g_wh2 + (size_t)row * 8);
    o[0] = make_float4(acc[0], acc[1], acc[2], acc[3]);
    o[1] = make_float4(acc[4], acc[5], acc[6], acc[7]);
}

// =====================================================================
// kD: layer-2 attention, row 0 only, chunked over j. grid (32,4), 512 thr.
// =====================================================================
__global__ __launch_bounds__(512) void kD() {
    __shared__ unsigned sbufD[2][NN];
    __shared__ unsigned sortedA[NN];
    __shared__ float E1s[NN], F1s[NN], PE[NN], PF[NN];
    __shared__ float s2s[NN];
    __shared__ float wsum2[16][2], off2[16][2];
    __shared__ float redbuf[16];
    __shared__ float wpart[4][8];
    __shared__ float bc0[1];

    const int b = blockIdx.x, jc = blockIdx.y, tid = threadIdx.x;
    const int lane = tid & 31, wid = tid >> 5;

    const float s1L = g_s1[b * NN + tid];
    const float s2L = g_s2[b * NN + tid];
    s2s[tid] = s2L;
    if (tid == 0) bc0[0] = s1L;

    float m = s1L;
#pragma unroll
    for (int o = 16; o >= 1; o >>= 1) m = fmaxf(m, __shfl_xor_sync(0xffffffffu, m, o));
    if (lane == 0) redbuf[wid] = m;
    __syncthreads();
    float M = redbuf[0];
#pragma unroll
    for (int w = 1; w < 16; w++) M = fmaxf(M, redbuf[w]);

    E1s[tid] = ex2f(s1L - M);
    F1s[tid] = ex2f(0.2f * (s1L - M));

    unsigned ka = (f2s(s1L) & KEYMASK) | (unsigned)tid;
    int p = 0;
    for (int k = 2; k <= NN; k <<= 1) {
        for (int s = k >> 1; s >= 1; s >>= 1) {
            const bool keepmin = (((tid & s) == 0) == ((tid & k) == 0));
            unsigned oa;
            if (s >= 32) {
                sbufD[p][tid] = ka;
                __syncthreads();
                oa = sbufD[p][tid ^ s];
                p ^= 1;
            } else {
                oa = __shfl_xor_sync(0xffffffffu, ka, s);
            }
            ka = ((ka < oa) == keepmin) ? ka : oa;
        }
    }
    sortedA[tid] = ka;
    {
        int ja = (int)(ka & 511u);
        PE[tid] = E1s[ja];
        PF[tid] = F1s[ja];
    }
    __syncthreads();
    scan2b(PE, PF, wsum2, off2, tid);
    const float TE = PE[NN - 1];

    if (tid < 128) {
        const float s2j = s2s[jc * 128 + tid];
        const int c = lb512(sortedA, f2s(-s2j) & KEYMASK);
        const float sumEge = TE - (c > 0 ? PE[c - 1] : 0.f);
        const float preF   = (c > 0 ? PF[c - 1] : 0.f);
        const float mj = lrelu02(M + s2j);
        const float E2 = ex2f(s2j + M - mj);
        const float F2 = ex2f(0.2f * (s2j + M) - mj);
        const float Z = E2 * sumEge + F2 * preF;

        const float s1L0 = bc0[0];
        const float e0 = (s1L0 + s2j >= 0.f) ? ex2f(s1L0 - M) * E2
                                             : ex2f(0.2f * (s1L0 - M)) * F2;
        const float wj = e0 / Z;

        const float4* w2 = reinterpret_cast<const float4*>(
            g_wh2 + ((size_t)(b * NN + jc * 128 + tid)) * 8);
        float4 wa = w2[0], wb = w2[1];
        float pv[8] = {wj * wa.x, wj * wa.y, wj * wa.z, wj * wa.w,
                       wj * wb.x, wj * wb.y, wj * wb.z, wj * wb.w};
#pragma unroll
        for (int d = 0; d < 8; d++) {
#pragma unroll
            for (int o = 16; o >= 1; o >>= 1)
                pv[d] += __shfl_xor_sync(0xffffffffu, pv[d], o);
        }
        if (lane == 0) {
#pragma unroll
            for (int d = 0; d < 8; d++) wpart[wid][d] = pv[d];
        }
    }
    __syncthreads();
    if (tid < 8) {
        g_h0p[b][jc][tid] = wpart[0][tid] + wpart[1][tid] + wpart[2][tid] + wpart[3][tid];
    }
}

// =====================================================================
// kE: elu(h0) -> concat feats -> lin1 -> prelu -> bn -> lin2
// =====================================================================
__global__ __launch_bounds__(256) void kE(const float* __restrict__ feats,
                                          const float* __restrict__ lin1w,
                                          const float* __restrict__ lin1b,
                                          const float* __restrict__ prelua,
                                          const float* __restrict__ gamma,
                                          const float* __restrict__ beta,
                                          const float* __restrict__ lin2w,
                                          const float* __restrict__ lin2b,
                                          float* __restrict__ out) {
    const int tid = threadIdx.x;
    const int b = tid >> 3, k = tid & 7;

    float gat[8];
#pragma unroll
    for (int d = 0; d < 8; d++) {
        float v = g_h0p[b][0][d] + g_h0p[b][1][d] + g_h0p[b][2][d] + g_h0p[b][3][d];
        gat[d] = eluf(v);
    }

    const float* w = lin1w + k * 136;
    const float* fr = feats + b * 128;
    float z = lin1b[k];
#pragma unroll 8
    for (int f = 0; f < 128; f++) z += fr[f] * w[f];
#pragma unroll
    for (int d = 0; d < 8; d++) z += gat[d] * w[128 + d];

    const float pa = prelua[0];
    z = (z >= 0.f) ? z : pa * z;
    z = z * rsqrtf(1.0f + 1e-5f) * gamma[k] + beta[k];

    float v = z * lin2w[k];
    v += __shfl_xor_sync(0xffffffffu, v, 4);
    v += __shfl_xor_sync(0xffffffffu, v, 2);
    v += __shfl_xor_sync(0xffffffffu, v, 1);
    if (k == 0) out[b] = v + lin2b[0];
}

// =====================================================================
extern "C" void kernel_launch(void* const* d_in, const int* in_sizes, int n_in,
                              void* d_out, int out_size) {
    (void)in_sizes; (void)n_in; (void)out_size;
    const float* feats  = (const float*)d_in[0];
    const float* nf     = (const float*)d_in[1];
    const float* Ws     = (const float*)d_in[2];
    const float* As     = (const float*)d_in[3];
    const float* Wout   = (const float*)d_in[4];
    const float* aout   = (const float*)d_in[5];
    const float* lin1w  = (const float*)d_in[6];
    const float* lin1b  = (const float*)d_in[7];
    const float* prelua = (const float*)d_in[8];
    const float* gamma  = (const float*)d_in[9];
    const float* beta   = (const float*)d_in[10];
    const float* lin2w  = (const float*)d_in[11];
    const float* lin2b  = (const float*)d_in[12];
    float* out = (float*)d_out;

    static bool attr_done = false;
    if (!attr_done) {
        cudaFuncSetAttribute(kA, cudaFuncAttributeMaxDynamicSharedMemorySize, KA_SMEM);
        cudaFuncSetAttribute(kB, cudaFuncAttributeMaxDynamicSharedMemorySize,
                             (int)sizeof(K2S));
        attr_done = true;
    }

    kA<<<128, 512, KA_SMEM>>>(nf, Ws);
    kB<<<dim3(32, 8), 512, sizeof(K2S)>>>(As);
    kC<<<128, 128>>>(Wout, aout);
    kD<<<dim3(32, 4), 512>>>();
    kE<<<1, 256>>>(feats, lin1w, lin1b, prelua, gamma, beta, lin2w, lin2b, out);
}